// round 1
// baseline (speedup 1.0000x reference)
#include <cuda_runtime.h>

#define NN   50000
#define EE   800000
#define FIN  256
#define HH   8
#define CC   32
#define HC   256   // HH*CC
#define NOUT 40
#define NEG_SLOPE 0.2f

// ---------------- device scratch (no runtime allocation allowed) ----------------
__device__ float g_h[(size_t)NN * HC];     // 51.2 MB : per-layer projected features
__device__ float g_act1[(size_t)NN * CC];  // layer-1 output (elu(mean)+b)
__device__ float g_act2[(size_t)NN * CC];  // layer-2 output
__device__ float g_asrc[NN * HH];
__device__ float g_adst[NN * HH];
__device__ int   g_deg[NN];
__device__ int   g_rowptr[NN + 1];
__device__ int   g_cursor[NN];
__device__ int   g_csr[EE];

// ---------------- CSR build ----------------
__global__ void zero_kernel() {
    int i = blockIdx.x * blockDim.x + threadIdx.x;
    if (i < NN) { g_deg[i] = 0; g_cursor[i] = 0; }
}

__global__ void count_kernel(const int* __restrict__ ei) {
    int e = blockIdx.x * blockDim.x + threadIdx.x;
    if (e < EE) atomicAdd(&g_deg[ei[EE + e]], 1);
}

// single-block exclusive scan of g_deg -> g_rowptr (N = 50000, ~49 chunks of 1024)
__global__ void scan_kernel() {
    __shared__ int sm[1024];
    __shared__ int s_off;
    if (threadIdx.x == 0) s_off = 0;
    __syncthreads();
    for (int base = 0; base < NN; base += 1024) {
        int i = base + threadIdx.x;
        int v = (i < NN) ? g_deg[i] : 0;
        sm[threadIdx.x] = v;
        __syncthreads();
        for (int o = 1; o < 1024; o <<= 1) {
            int t = (threadIdx.x >= o) ? sm[threadIdx.x - o] : 0;
            __syncthreads();
            sm[threadIdx.x] += t;
            __syncthreads();
        }
        if (i < NN) g_rowptr[i] = s_off + sm[threadIdx.x] - v;  // exclusive
        __syncthreads();
        if (threadIdx.x == 0) s_off += sm[1023];
        __syncthreads();
    }
    if (threadIdx.x == 0) g_rowptr[NN] = s_off;
}

__global__ void fill_kernel(const int* __restrict__ ei) {
    int e = blockIdx.x * blockDim.x + threadIdx.x;
    if (e < EE) {
        int src = ei[e];
        int dst = ei[EE + e];
        int pos = atomicAdd(&g_cursor[dst], 1);
        g_csr[g_rowptr[dst] + pos] = src;
    }
}

// ---------------- fp32 tiled GEMM: C[M,Nc] = A[M,K] @ B[K,Nc] ----------------
__global__ __launch_bounds__(256) void sgemm64(const float* __restrict__ A,
                                               const float* __restrict__ B,
                                               float* __restrict__ Cmat,
                                               int M, int Nc, int K) {
    const int BM = 64, BN = 64, BK = 16;
    __shared__ float As[BK][BM];
    __shared__ float Bs[BK][BN];
    int tid = threadIdx.x;
    int bm = blockIdx.y * BM;
    int bn = blockIdx.x * BN;
    int tx = tid & 15, ty = tid >> 4;
    int arow = tid >> 2;
    int acol = (tid & 3) << 2;
    int brow = tid >> 4;
    int bcol = (tid & 15) << 2;
    float acc[4][4] = {};
    for (int k0 = 0; k0 < K; k0 += BK) {
        float4 av = make_float4(0.f, 0.f, 0.f, 0.f);
        if (bm + arow < M)
            av = *(const float4*)(A + (size_t)(bm + arow) * K + k0 + acol);
        As[acol + 0][arow] = av.x;
        As[acol + 1][arow] = av.y;
        As[acol + 2][arow] = av.z;
        As[acol + 3][arow] = av.w;
        float4 bv = *(const float4*)(B + (size_t)(k0 + brow) * Nc + bn + bcol);
        *(float4*)&Bs[brow][bcol] = bv;
        __syncthreads();
#pragma unroll
        for (int kk = 0; kk < BK; kk++) {
            float4 a = *(const float4*)&As[kk][ty * 4];
            float4 b = *(const float4*)&Bs[kk][tx * 4];
            acc[0][0] += a.x * b.x; acc[0][1] += a.x * b.y; acc[0][2] += a.x * b.z; acc[0][3] += a.x * b.w;
            acc[1][0] += a.y * b.x; acc[1][1] += a.y * b.y; acc[1][2] += a.y * b.z; acc[1][3] += a.y * b.w;
            acc[2][0] += a.z * b.x; acc[2][1] += a.z * b.y; acc[2][2] += a.z * b.z; acc[2][3] += a.z * b.w;
            acc[3][0] += a.w * b.x; acc[3][1] += a.w * b.y; acc[3][2] += a.w * b.z; acc[3][3] += a.w * b.w;
        }
        __syncthreads();
    }
#pragma unroll
    for (int i = 0; i < 4; i++) {
        int row = bm + ty * 4 + i;
        if (row < M) {
            float4 v = make_float4(acc[i][0], acc[i][1], acc[i][2], acc[i][3]);
            *(float4*)(Cmat + (size_t)row * Nc + bn + tx * 4) = v;
        }
    }
}

// ---------------- attention coefficients: alpha_src/dst per (node, head) ----------------
__global__ void alpha_kernel(const float* __restrict__ hbuf,
                             const float* __restrict__ a_src,
                             const float* __restrict__ a_dst) {
    int idx = blockIdx.x * blockDim.x + threadIdx.x;
    if (idx >= NN * HH) return;
    int hd = idx & (HH - 1);
    const float4* hp = (const float4*)(hbuf + (size_t)idx * CC);  // idx*32 == n*256 + hd*32
    const float4* as = (const float4*)(a_src + hd * CC);
    const float4* ad = (const float4*)(a_dst + hd * CC);
    float s1 = 0.f, s2 = 0.f;
#pragma unroll
    for (int i = 0; i < 8; i++) {
        float4 v = hp[i], a = as[i], d = ad[i];
        s1 += v.x * a.x + v.y * a.y + v.z * a.z + v.w * a.w;
        s2 += v.x * d.x + v.y * d.y + v.z * d.z + v.w * d.w;
    }
    g_asrc[idx] = s1;
    g_adst[idx] = s2;
}

__device__ __forceinline__ float lrelu(float e) { return e > 0.f ? e : NEG_SLOPE * e; }

// ---------------- gather-style aggregation: one warp per dst node ----------------
// pass1: per-head softmax denominator (lanes in a quad split the edges, shfl reduce)
// pass2: weighted accumulation of h[src] into registers; head-mean + bias + ELU fused.
__global__ __launch_bounds__(256) void aggregate_kernel(const float* __restrict__ hbuf,
                                                        const float* __restrict__ asrc,
                                                        const float* __restrict__ adst,
                                                        const float* __restrict__ bias,
                                                        float* __restrict__ outbuf) {
    int w = (blockIdx.x * blockDim.x + threadIdx.x) >> 5;
    int lane = threadIdx.x & 31;
    if (w >= NN) return;
    int dst = w;
    int beg = g_rowptr[dst], end = g_rowptr[dst + 1];
    int hd = lane >> 2;           // head 0..7
    int cb = (lane & 3) * 8;      // channel base within head: 0,8,16,24
    float adst_h = adst[dst * HH + hd];

    // self-loop term (PyG add_self_loops)
    float es = lrelu(asrc[dst * HH + hd] + adst_h);
    float ex_self = __expf(es);

    // pass 1: denominator (skip max-subtraction; e is O(1), ratio is invariant)
    float s = 0.f;
    for (int i = beg + (lane & 3); i < end; i += 4) {
        int src = g_csr[i];
        s += __expf(lrelu(asrc[src * HH + hd] + adst_h));
    }
    s += __shfl_xor_sync(0xffffffffu, s, 1);
    s += __shfl_xor_sync(0xffffffffu, s, 2);
    s += ex_self;
    float inv = 1.f / s;

    // pass 2: weighted accumulate (8 channels per lane)
    float acc[8] = {0.f, 0.f, 0.f, 0.f, 0.f, 0.f, 0.f, 0.f};
    {
        float al = ex_self * inv;
        const float4* hr = (const float4*)(hbuf + (size_t)dst * HC + hd * CC + cb);
        float4 v0 = hr[0], v1 = hr[1];
        acc[0] += al * v0.x; acc[1] += al * v0.y; acc[2] += al * v0.z; acc[3] += al * v0.w;
        acc[4] += al * v1.x; acc[5] += al * v1.y; acc[6] += al * v1.z; acc[7] += al * v1.w;
    }
    for (int i = beg; i < end; ++i) {
        int src = g_csr[i];
        float al = __expf(lrelu(asrc[src * HH + hd] + adst_h)) * inv;
        const float4* hr = (const float4*)(hbuf + (size_t)src * HC + hd * CC + cb);
        float4 v0 = hr[0], v1 = hr[1];
        acc[0] += al * v0.x; acc[1] += al * v0.y; acc[2] += al * v0.z; acc[3] += al * v0.w;
        acc[4] += al * v1.x; acc[5] += al * v1.y; acc[6] += al * v1.z; acc[7] += al * v1.w;
    }

    // mean over heads: reduce across lanes differing in head bits (2,3,4)
#pragma unroll
    for (int j = 0; j < 8; j++) {
        float v = acc[j];
        v += __shfl_xor_sync(0xffffffffu, v, 4);
        v += __shfl_xor_sync(0xffffffffu, v, 8);
        v += __shfl_xor_sync(0xffffffffu, v, 16);
        acc[j] = v * 0.125f;
    }

    if (lane < 4) {
        float o[8];
#pragma unroll
        for (int j = 0; j < 8; j++) {
            float v = acc[j] + bias[cb + j];
            o[j] = v > 0.f ? v : (__expf(v) - 1.f);   // ELU
        }
        float4* op = (float4*)(outbuf + (size_t)dst * CC + cb);
        op[0] = make_float4(o[0], o[1], o[2], o[3]);
        op[1] = make_float4(o[4], o[5], o[6], o[7]);
    }
}

// ---------------- final projection (32->40) + log_softmax, one thread per node ----------------
__global__ __launch_bounds__(128) void final_kernel(const float* __restrict__ act,
                                                    const float* __restrict__ Wo,
                                                    const float* __restrict__ bo,
                                                    float* __restrict__ out) {
    __shared__ float sW[CC * NOUT];
    __shared__ float sb[NOUT];
    for (int i = threadIdx.x; i < CC * NOUT; i += blockDim.x) sW[i] = Wo[i];
    for (int i = threadIdx.x; i < NOUT; i += blockDim.x) sb[i] = bo[i];
    __syncthreads();
    int n = blockIdx.x * blockDim.x + threadIdx.x;
    if (n >= NN) return;
    float xr[CC];
    const float4* ap = (const float4*)(act + (size_t)n * CC);
#pragma unroll
    for (int i = 0; i < 8; i++) {
        float4 v = ap[i];
        xr[4 * i + 0] = v.x; xr[4 * i + 1] = v.y; xr[4 * i + 2] = v.z; xr[4 * i + 3] = v.w;
    }
    float lg[NOUT];
#pragma unroll
    for (int j = 0; j < NOUT; j++) {
        float sum = sb[j];
#pragma unroll
        for (int c = 0; c < CC; c++) sum += xr[c] * sW[c * NOUT + j];
        lg[j] = sum;
    }
    float m = lg[0];
#pragma unroll
    for (int j = 1; j < NOUT; j++) m = fmaxf(m, lg[j]);
    float se = 0.f;
#pragma unroll
    for (int j = 0; j < NOUT; j++) se += __expf(lg[j] - m);
    float lse = m + __logf(se);
    float* op = out + (size_t)n * NOUT;
#pragma unroll
    for (int j = 0; j < NOUT; j++) op[j] = lg[j] - lse;
}

// ---------------- launch ----------------
extern "C" void kernel_launch(void* const* d_in, const int* in_sizes, int n_in,
                              void* d_out, int out_size) {
    const float* x   = (const float*)d_in[0];
    const int*   ei  = (const int*)d_in[1];
    const float* W1  = (const float*)d_in[2];
    const float* as1 = (const float*)d_in[3];
    const float* ad1 = (const float*)d_in[4];
    const float* b1  = (const float*)d_in[5];
    const float* W2  = (const float*)d_in[6];
    const float* as2 = (const float*)d_in[7];
    const float* ad2 = (const float*)d_in[8];
    const float* b2  = (const float*)d_in[9];
    const float* Wo  = (const float*)d_in[10];
    const float* bo  = (const float*)d_in[11];
    float* out = (float*)d_out;

    float *hbuf, *act1, *act2, *pasrc, *padst;
    cudaGetSymbolAddress((void**)&hbuf, g_h);
    cudaGetSymbolAddress((void**)&act1, g_act1);
    cudaGetSymbolAddress((void**)&act2, g_act2);
    cudaGetSymbolAddress((void**)&pasrc, g_asrc);
    cudaGetSymbolAddress((void**)&padst, g_adst);

    // CSR build (graph is an input; rebuilt every call for determinism rules)
    zero_kernel<<<(NN + 255) / 256, 256>>>();
    count_kernel<<<(EE + 255) / 256, 256>>>(ei);
    scan_kernel<<<1, 1024>>>();
    fill_kernel<<<(EE + 255) / 256, 256>>>(ei);

    dim3 g1(HC / 64, (NN + 63) / 64);

    // ---- layer 1 ----
    sgemm64<<<g1, 256>>>(x, W1, hbuf, NN, HC, FIN);
    alpha_kernel<<<(NN * HH + 255) / 256, 256>>>(hbuf, as1, ad1);
    aggregate_kernel<<<(NN * 32 + 255) / 256, 256>>>(hbuf, pasrc, padst, b1, act1);

    // ---- layer 2 ----
    sgemm64<<<g1, 256>>>(act1, W2, hbuf, NN, HC, CC);
    alpha_kernel<<<(NN * HH + 255) / 256, 256>>>(hbuf, as2, ad2);
    aggregate_kernel<<<(NN * 32 + 255) / 256, 256>>>(hbuf, pasrc, padst, b2, act2);

    // ---- output head ----
    final_kernel<<<(NN + 127) / 128, 128>>>(act2, Wo, bo, out);
}

// round 2
// speedup vs baseline: 1.2275x; 1.2275x over previous
#include <cuda_runtime.h>

#define NN   50000
#define EE   800000
#define FIN  256
#define HH   8
#define CC   32
#define HC   256   // HH*CC
#define NOUT 40
#define NEG_SLOPE 0.2f
#define NB   ((NN + 255) / 256)   // 196 blocks for scan

// ---------------- device scratch (no runtime allocation allowed) ----------------
__device__ float g_h[(size_t)NN * HC];     // 51.2 MB : per-layer projected features
__device__ float g_act1[(size_t)NN * CC];
__device__ float g_act2[(size_t)NN * CC];
__device__ float g_asrc[NN * HH];
__device__ float g_adst[NN * HH];
__device__ int   g_deg[NN];
__device__ int   g_rowptr[NN + 1];
__device__ int   g_cursor[NN];
__device__ int   g_csr[EE];
__device__ int   g_bsum[NB];
__device__ int   g_boff[NB];

// ---------------- CSR build ----------------
__global__ void zero_kernel() {
    int i = blockIdx.x * blockDim.x + threadIdx.x;
    if (i < NN) g_deg[i] = 0;
}

__global__ void count_kernel(const int* __restrict__ ei) {
    int e = blockIdx.x * blockDim.x + threadIdx.x;
    if (e < EE) atomicAdd(&g_deg[ei[EE + e]], 1);
}

// per-block sums of deg
__global__ void degsum_kernel() {
    __shared__ int sm[256];
    int i = blockIdx.x * 256 + threadIdx.x;
    int v = (i < NN) ? g_deg[i] : 0;
    sm[threadIdx.x] = v;
    __syncthreads();
    for (int o = 128; o > 0; o >>= 1) {
        if (threadIdx.x < o) sm[threadIdx.x] += sm[threadIdx.x + o];
        __syncthreads();
    }
    if (threadIdx.x == 0) g_bsum[blockIdx.x] = sm[0];
}

// one block scans the 196 partial sums (exclusive)
__global__ void scanb_kernel() {
    __shared__ int sm[256];
    int t = threadIdx.x;
    int v = (t < NB) ? g_bsum[t] : 0;
    sm[t] = v;
    __syncthreads();
    for (int o = 1; o < 256; o <<= 1) {
        int u = (t >= o) ? sm[t - o] : 0;
        __syncthreads();
        sm[t] += u;
        __syncthreads();
    }
    if (t < NB) g_boff[t] = sm[t] - v;
}

// per-block local scan + global offset -> rowptr; also zero cursor
__global__ void scanc_kernel() {
    __shared__ int sm[256];
    int b = blockIdx.x, t = threadIdx.x;
    int i = b * 256 + t;
    int v = (i < NN) ? g_deg[i] : 0;
    sm[t] = v;
    __syncthreads();
    for (int o = 1; o < 256; o <<= 1) {
        int u = (t >= o) ? sm[t - o] : 0;
        __syncthreads();
        sm[t] += u;
        __syncthreads();
    }
    int excl = g_boff[b] + sm[t] - v;
    if (i < NN) { g_rowptr[i] = excl; g_cursor[i] = 0; }
    if (i == NN - 1) g_rowptr[NN] = excl + v;
}

__global__ void fill_kernel(const int* __restrict__ ei) {
    int e = blockIdx.x * blockDim.x + threadIdx.x;
    if (e < EE) {
        int src = ei[e];
        int dst = ei[EE + e];
        int pos = atomicAdd(&g_cursor[dst], 1);
        g_csr[g_rowptr[dst] + pos] = src;
    }
}

// ---------------- fp32 tiled GEMM: C[M,Nc] = A[M,K] @ B[K,Nc] ----------------
// BM=128, BN=128, BK=16, 256 threads, 8x8 accum in raked 2x2 (tx*4 / 64+tx*4) layout.
__global__ __launch_bounds__(256) void sgemm128(const float* __restrict__ A,
                                                const float* __restrict__ B,
                                                float* __restrict__ Cmat,
                                                int M, int Nc, int K) {
    const int BM = 128, BN = 128, BK = 16;
    __shared__ float As[BK][BM];
    __shared__ float Bs[BK][BN];
    int tid = threadIdx.x;
    int bm = blockIdx.y * BM;
    int bn = blockIdx.x * BN;
    int ar = tid >> 2, ac = (tid & 3) << 2;     // A: 2 float4 per thread (rows ar, ar+64)
    int br = tid >> 5, bc = (tid & 31) << 2;    // B: 2 float4 per thread (rows br, br+8)
    int tx = tid & 15, ty = tid >> 4;           // 16x16 thread grid
    float acc[8][8] = {};
    for (int k0 = 0; k0 < K; k0 += BK) {
#pragma unroll
        for (int t = 0; t < 2; t++) {
            int row = bm + ar + t * 64;
            float4 v = make_float4(0.f, 0.f, 0.f, 0.f);
            if (row < M) v = *(const float4*)(A + (size_t)row * K + k0 + ac);
            As[ac + 0][ar + t * 64] = v.x;
            As[ac + 1][ar + t * 64] = v.y;
            As[ac + 2][ar + t * 64] = v.z;
            As[ac + 3][ar + t * 64] = v.w;
        }
#pragma unroll
        for (int t = 0; t < 2; t++) {
            float4 v = *(const float4*)(B + (size_t)(k0 + br + t * 8) * Nc + bn + bc);
            *(float4*)&Bs[br + t * 8][bc] = v;
        }
        __syncthreads();
#pragma unroll
        for (int kk = 0; kk < BK; kk++) {
            float a[8], b[8];
            *(float4*)(a)     = *(const float4*)&As[kk][ty * 4];
            *(float4*)(a + 4) = *(const float4*)&As[kk][64 + ty * 4];
            *(float4*)(b)     = *(const float4*)&Bs[kk][tx * 4];
            *(float4*)(b + 4) = *(const float4*)&Bs[kk][64 + tx * 4];
#pragma unroll
            for (int i = 0; i < 8; i++)
#pragma unroll
                for (int j = 0; j < 8; j++)
                    acc[i][j] += a[i] * b[j];
        }
        __syncthreads();
    }
    // store: row groups {bm+ty*4+i, bm+64+ty*4+i}, col groups {bn+tx*4, bn+64+tx*4}
#pragma unroll
    for (int g = 0; g < 2; g++) {
#pragma unroll
        for (int i = 0; i < 4; i++) {
            int row = bm + g * 64 + ty * 4 + i;
            if (row < M) {
                float* cp = Cmat + (size_t)row * Nc + bn;
                *(float4*)(cp + tx * 4)      = make_float4(acc[g*4+i][0], acc[g*4+i][1], acc[g*4+i][2], acc[g*4+i][3]);
                *(float4*)(cp + 64 + tx * 4) = make_float4(acc[g*4+i][4], acc[g*4+i][5], acc[g*4+i][6], acc[g*4+i][7]);
            }
        }
    }
}

// ---------------- attention coefficients ----------------
__global__ void alpha_kernel(const float* __restrict__ hbuf,
                             const float* __restrict__ a_src,
                             const float* __restrict__ a_dst) {
    int idx = blockIdx.x * blockDim.x + threadIdx.x;
    if (idx >= NN * HH) return;
    int hd = idx & (HH - 1);
    const float4* hp = (const float4*)(hbuf + (size_t)idx * CC);
    const float4* as = (const float4*)(a_src + hd * CC);
    const float4* ad = (const float4*)(a_dst + hd * CC);
    float s1 = 0.f, s2 = 0.f;
#pragma unroll
    for (int i = 0; i < 8; i++) {
        float4 v = hp[i], a = as[i], d = ad[i];
        s1 += v.x * a.x + v.y * a.y + v.z * a.z + v.w * a.w;
        s2 += v.x * d.x + v.y * d.y + v.z * d.z + v.w * d.w;
    }
    g_asrc[idx] = s1;
    g_adst[idx] = s2;
}

__device__ __forceinline__ float lrelu(float e) { return e > 0.f ? e : NEG_SLOPE * e; }

// ---------------- single-pass gather aggregation: one warp per dst node ----------------
// out = (Sigma_e ex_e * h[src_e]) / (Sigma_e ex_e)  -- normalize AFTER accumulation.
__global__ __launch_bounds__(256) void aggregate_kernel(const float* __restrict__ hbuf,
                                                        const float* __restrict__ asrc,
                                                        const float* __restrict__ adst,
                                                        const float* __restrict__ bias,
                                                        float* __restrict__ outbuf) {
    int w = (blockIdx.x * blockDim.x + threadIdx.x) >> 5;
    int lane = threadIdx.x & 31;
    if (w >= NN) return;
    int dst = w;
    int beg = g_rowptr[dst], end = g_rowptr[dst + 1];
    int hd = lane >> 2;           // head 0..7
    int cb = (lane & 3) * 8;      // channel base within head
    float adst_h = adst[dst * HH + hd];

    // self-loop seeds the accumulators
    float ex_self = __expf(lrelu(asrc[dst * HH + hd] + adst_h));
    float s = ex_self;
    float acc[8];
    {
        const float4* hr = (const float4*)(hbuf + (size_t)dst * HC + hd * CC + cb);
        float4 v0 = hr[0], v1 = hr[1];
        acc[0] = ex_self * v0.x; acc[1] = ex_self * v0.y; acc[2] = ex_self * v0.z; acc[3] = ex_self * v0.w;
        acc[4] = ex_self * v1.x; acc[5] = ex_self * v1.y; acc[6] = ex_self * v1.z; acc[7] = ex_self * v1.w;
    }

    for (int i = beg; i < end; ++i) {
        int src = g_csr[i];                     // broadcast across warp
        float ex = __expf(lrelu(asrc[src * HH + hd] + adst_h));
        s += ex;
        const float4* hr = (const float4*)(hbuf + (size_t)src * HC + hd * CC + cb);
        float4 v0 = hr[0], v1 = hr[1];
        acc[0] += ex * v0.x; acc[1] += ex * v0.y; acc[2] += ex * v0.z; acc[3] += ex * v0.w;
        acc[4] += ex * v1.x; acc[5] += ex * v1.y; acc[6] += ex * v1.z; acc[7] += ex * v1.w;
    }

    float inv = 1.f / s;
#pragma unroll
    for (int j = 0; j < 8; j++) acc[j] *= inv;

    // mean over heads: reduce across lanes differing in head bits
#pragma unroll
    for (int j = 0; j < 8; j++) {
        float v = acc[j];
        v += __shfl_xor_sync(0xffffffffu, v, 4);
        v += __shfl_xor_sync(0xffffffffu, v, 8);
        v += __shfl_xor_sync(0xffffffffu, v, 16);
        acc[j] = v * 0.125f;
    }

    if (lane < 4) {
        float o[8];
#pragma unroll
        for (int j = 0; j < 8; j++) {
            float v = acc[j] + bias[cb + j];
            o[j] = v > 0.f ? v : (__expf(v) - 1.f);   // ELU
        }
        float4* op = (float4*)(outbuf + (size_t)dst * CC + cb);
        op[0] = make_float4(o[0], o[1], o[2], o[3]);
        op[1] = make_float4(o[4], o[5], o[6], o[7]);
    }
}

// ---------------- final projection (32->40) + log_softmax ----------------
__global__ __launch_bounds__(128) void final_kernel(const float* __restrict__ act,
                                                    const float* __restrict__ Wo,
                                                    const float* __restrict__ bo,
                                                    float* __restrict__ out) {
    __shared__ float sW[CC * NOUT];
    __shared__ float sb[NOUT];
    for (int i = threadIdx.x; i < CC * NOUT; i += blockDim.x) sW[i] = Wo[i];
    for (int i = threadIdx.x; i < NOUT; i += blockDim.x) sb[i] = bo[i];
    __syncthreads();
    int n = blockIdx.x * blockDim.x + threadIdx.x;
    if (n >= NN) return;
    float xr[CC];
    const float4* ap = (const float4*)(act + (size_t)n * CC);
#pragma unroll
    for (int i = 0; i < 8; i++) {
        float4 v = ap[i];
        xr[4 * i + 0] = v.x; xr[4 * i + 1] = v.y; xr[4 * i + 2] = v.z; xr[4 * i + 3] = v.w;
    }
    float lg[NOUT];
#pragma unroll
    for (int j = 0; j < NOUT; j++) {
        float sum = sb[j];
#pragma unroll
        for (int c = 0; c < CC; c++) sum += xr[c] * sW[c * NOUT + j];
        lg[j] = sum;
    }
    float m = lg[0];
#pragma unroll
    for (int j = 1; j < NOUT; j++) m = fmaxf(m, lg[j]);
    float se = 0.f;
#pragma unroll
    for (int j = 0; j < NOUT; j++) se += __expf(lg[j] - m);
    float lse = m + __logf(se);
    float* op = out + (size_t)n * NOUT;
#pragma unroll
    for (int j = 0; j < NOUT; j++) op[j] = lg[j] - lse;
}

// ---------------- launch ----------------
extern "C" void kernel_launch(void* const* d_in, const int* in_sizes, int n_in,
                              void* d_out, int out_size) {
    const float* x   = (const float*)d_in[0];
    const int*   ei  = (const int*)d_in[1];
    const float* W1  = (const float*)d_in[2];
    const float* as1 = (const float*)d_in[3];
    const float* ad1 = (const float*)d_in[4];
    const float* b1  = (const float*)d_in[5];
    const float* W2  = (const float*)d_in[6];
    const float* as2 = (const float*)d_in[7];
    const float* ad2 = (const float*)d_in[8];
    const float* b2  = (const float*)d_in[9];
    const float* Wo  = (const float*)d_in[10];
    const float* bo  = (const float*)d_in[11];
    float* out = (float*)d_out;

    float *hbuf, *act1, *act2, *pasrc, *padst;
    cudaGetSymbolAddress((void**)&hbuf, g_h);
    cudaGetSymbolAddress((void**)&act1, g_act1);
    cudaGetSymbolAddress((void**)&act2, g_act2);
    cudaGetSymbolAddress((void**)&pasrc, g_asrc);
    cudaGetSymbolAddress((void**)&padst, g_adst);

    // CSR build
    zero_kernel<<<NB, 256>>>();
    count_kernel<<<(EE + 255) / 256, 256>>>(ei);
    degsum_kernel<<<NB, 256>>>();
    scanb_kernel<<<1, 256>>>();
    scanc_kernel<<<NB, 256>>>();
    fill_kernel<<<(EE + 255) / 256, 256>>>(ei);

    dim3 g1(HC / 128, (NN + 127) / 128);

    // ---- layer 1 ----
    sgemm128<<<g1, 256>>>(x, W1, hbuf, NN, HC, FIN);
    alpha_kernel<<<(NN * HH + 255) / 256, 256>>>(hbuf, as1, ad1);
    aggregate_kernel<<<(NN * 32 + 255) / 256, 256>>>(hbuf, pasrc, padst, b1, act1);

    // ---- layer 2 ----
    sgemm128<<<g1, 256>>>(act1, W2, hbuf, NN, HC, CC);
    alpha_kernel<<<(NN * HH + 255) / 256, 256>>>(hbuf, as2, ad2);
    aggregate_kernel<<<(NN * 32 + 255) / 256, 256>>>(hbuf, pasrc, padst, b2, act2);

    // ---- output head ----
    final_kernel<<<(NN + 127) / 128, 128>>>(act2, Wo, bo, out);
}

// round 3
// speedup vs baseline: 1.7159x; 1.3978x over previous
#include <cuda_runtime.h>
#include <cuda_bf16.h>
#include <mma.h>

using namespace nvcuda;

#define NN   50000
#define EE   800000
#define FIN  256
#define HH   8
#define CC   32
#define HC   256   // HH*CC
#define NOUT 40
#define NEG_SLOPE 0.2f
#define NB   ((NN + 255) / 256)

// ---------------- device scratch ----------------
__device__ __nv_bfloat16 g_h[(size_t)NN * HC];   // 25.6 MB : projected features (bf16)
__device__ float g_act1[(size_t)NN * CC];
__device__ float g_act2[(size_t)NN * CC];
__device__ float g_asrc[NN * HH];
__device__ float g_adst[NN * HH];
__device__ int   g_deg[NN];
__device__ int   g_rowptr[NN + 1];
__device__ int   g_cursor[NN];
__device__ int   g_csr[EE];
__device__ int   g_bsum[NB];
__device__ int   g_boff[NB];

// ---------------- CSR build ----------------
__global__ void zero_kernel() {
    int i = blockIdx.x * blockDim.x + threadIdx.x;
    if (i < NN) g_deg[i] = 0;
}

__global__ void count_kernel(const int* __restrict__ ei) {
    int e = blockIdx.x * blockDim.x + threadIdx.x;
    if (e < EE) atomicAdd(&g_deg[ei[EE + e]], 1);
}

__global__ void degsum_kernel() {
    __shared__ int sm[256];
    int i = blockIdx.x * 256 + threadIdx.x;
    int v = (i < NN) ? g_deg[i] : 0;
    sm[threadIdx.x] = v;
    __syncthreads();
    for (int o = 128; o > 0; o >>= 1) {
        if (threadIdx.x < o) sm[threadIdx.x] += sm[threadIdx.x + o];
        __syncthreads();
    }
    if (threadIdx.x == 0) g_bsum[blockIdx.x] = sm[0];
}

__global__ void scanb_kernel() {
    __shared__ int sm[256];
    int t = threadIdx.x;
    int v = (t < NB) ? g_bsum[t] : 0;
    sm[t] = v;
    __syncthreads();
    for (int o = 1; o < 256; o <<= 1) {
        int u = (t >= o) ? sm[t - o] : 0;
        __syncthreads();
        sm[t] += u;
        __syncthreads();
    }
    if (t < NB) g_boff[t] = sm[t] - v;
}

__global__ void scanc_kernel() {
    __shared__ int sm[256];
    int b = blockIdx.x, t = threadIdx.x;
    int i = b * 256 + t;
    int v = (i < NN) ? g_deg[i] : 0;
    sm[t] = v;
    __syncthreads();
    for (int o = 1; o < 256; o <<= 1) {
        int u = (t >= o) ? sm[t - o] : 0;
        __syncthreads();
        sm[t] += u;
        __syncthreads();
    }
    int excl = g_boff[b] + sm[t] - v;
    if (i < NN) { g_rowptr[i] = excl; g_cursor[i] = 0; }
    if (i == NN - 1) g_rowptr[NN] = excl + v;
}

__global__ void fill_kernel(const int* __restrict__ ei) {
    int e = blockIdx.x * blockDim.x + threadIdx.x;
    if (e < EE) {
        int src = ei[e];
        int dst = ei[EE + e];
        int pos = atomicAdd(&g_cursor[dst], 1);
        g_csr[g_rowptr[dst] + pos] = src;
    }
}

// ---------------- bf16 tensor-core GEMM ----------------
// C[M,256](bf16) = A[M,K](fp32) @ B[K,256](fp32), fp32 accumulate.
// BM=128, BN=128, BK=32, 256 threads = 8 warps in 4x2; each warp 32x64 (2x4 wmma tiles).
#define GBM 128
#define GBN 128
#define GBK 32
__global__ __launch_bounds__(256) void gemm_bf16(const float* __restrict__ A,
                                                 const float* __restrict__ B,
                                                 __nv_bfloat16* __restrict__ Cmat,
                                                 int M, int Nc, int K) {
    __shared__ __nv_bfloat16 As[GBM][GBK + 8];   // ldm 40
    __shared__ __nv_bfloat16 Bs[GBK][GBN + 8];   // ldm 136
    __shared__ float stage[8][16 * 20];          // per-warp 16x16 staging, ldm 20

    int tid = threadIdx.x;
    int wid = tid >> 5;
    int lane = tid & 31;
    int wm = wid >> 1;      // 0..3
    int wn = wid & 1;       // 0..1
    int bm = blockIdx.y * GBM;
    int bn = blockIdx.x * GBN;

    wmma::fragment<wmma::accumulator, 16, 16, 16, float> acc[2][4];
#pragma unroll
    for (int i = 0; i < 2; i++)
#pragma unroll
        for (int j = 0; j < 4; j++)
            wmma::fill_fragment(acc[i][j], 0.0f);

    int arow = tid >> 1;            // 0..127
    int acol = (tid & 1) * 16;      // 0 or 16
    int brow = tid >> 3;            // 0..31
    int bcol = (tid & 7) * 16;      // 0..112

    for (int k0 = 0; k0 < K; k0 += GBK) {
        // A tile: 128x32 fp32 -> bf16 smem (zero-fill OOB rows)
        {
            float4 v[4];
            if (bm + arow < M) {
                const float4* ap = (const float4*)(A + (size_t)(bm + arow) * K + k0 + acol);
#pragma unroll
                for (int t = 0; t < 4; t++) v[t] = ap[t];
            } else {
#pragma unroll
                for (int t = 0; t < 4; t++) v[t] = make_float4(0.f, 0.f, 0.f, 0.f);
            }
            __nv_bfloat16* dstp = &As[arow][acol];
#pragma unroll
            for (int t = 0; t < 4; t++) {
                dstp[4 * t + 0] = __float2bfloat16_rn(v[t].x);
                dstp[4 * t + 1] = __float2bfloat16_rn(v[t].y);
                dstp[4 * t + 2] = __float2bfloat16_rn(v[t].z);
                dstp[4 * t + 3] = __float2bfloat16_rn(v[t].w);
            }
        }
        // B tile: 32x128 fp32 -> bf16 smem
        {
            const float4* bp = (const float4*)(B + (size_t)(k0 + brow) * Nc + bn + bcol);
            __nv_bfloat16* dstp = &Bs[brow][bcol];
#pragma unroll
            for (int t = 0; t < 4; t++) {
                float4 v = bp[t];
                dstp[4 * t + 0] = __float2bfloat16_rn(v.x);
                dstp[4 * t + 1] = __float2bfloat16_rn(v.y);
                dstp[4 * t + 2] = __float2bfloat16_rn(v.z);
                dstp[4 * t + 3] = __float2bfloat16_rn(v.w);
            }
        }
        __syncthreads();
#pragma unroll
        for (int ks = 0; ks < GBK; ks += 16) {
            wmma::fragment<wmma::matrix_a, 16, 16, 16, __nv_bfloat16, wmma::row_major> af[2];
#pragma unroll
            for (int i = 0; i < 2; i++)
                wmma::load_matrix_sync(af[i], &As[wm * 32 + i * 16][ks], GBK + 8);
            wmma::fragment<wmma::matrix_b, 16, 16, 16, __nv_bfloat16, wmma::row_major> bf[4];
#pragma unroll
            for (int j = 0; j < 4; j++)
                wmma::load_matrix_sync(bf[j], &Bs[ks][wn * 64 + j * 16], GBN + 8);
#pragma unroll
            for (int i = 0; i < 2; i++)
#pragma unroll
                for (int j = 0; j < 4; j++)
                    wmma::mma_sync(acc[i][j], af[i], bf[j], acc[i][j]);
        }
        __syncthreads();
    }

    // epilogue: per-warp fp32 staging -> bf16 global
    float* st = &stage[wid][0];
    int lr = lane >> 1;             // 0..15
    int lc = (lane & 1) * 8;        // 0 or 8
#pragma unroll
    for (int i = 0; i < 2; i++) {
#pragma unroll
        for (int j = 0; j < 4; j++) {
            wmma::store_matrix_sync(st, acc[i][j], 20, wmma::mem_row_major);
            __syncwarp();
            int row = bm + wm * 32 + i * 16 + lr;
            int col = bn + wn * 64 + j * 16 + lc;
            if (row < M) {
                __nv_bfloat16 tmp[8];
#pragma unroll
                for (int t = 0; t < 8; t++)
                    tmp[t] = __float2bfloat16_rn(st[lr * 20 + lc + t]);
                *(uint4*)(Cmat + (size_t)row * Nc + col) = *(uint4*)tmp;
            }
            __syncwarp();
        }
    }
}

// ---------------- attention coefficients (bf16 h) ----------------
__global__ void alpha_kernel(const __nv_bfloat16* __restrict__ hbuf,
                             const float* __restrict__ a_src,
                             const float* __restrict__ a_dst) {
    int idx = blockIdx.x * blockDim.x + threadIdx.x;
    if (idx >= NN * HH) return;
    int hd = idx & (HH - 1);
    const __nv_bfloat162* hp = (const __nv_bfloat162*)(hbuf + (size_t)idx * CC);
    const float* as = a_src + hd * CC;
    const float* ad = a_dst + hd * CC;
    float s1 = 0.f, s2 = 0.f;
#pragma unroll
    for (int i = 0; i < 16; i++) {
        float2 v = __bfloat1622float2(hp[i]);
        s1 += v.x * as[2 * i] + v.y * as[2 * i + 1];
        s2 += v.x * ad[2 * i] + v.y * ad[2 * i + 1];
    }
    g_asrc[idx] = s1;
    g_adst[idx] = s2;
}

__device__ __forceinline__ float lrelu(float e) { return e > 0.f ? e : NEG_SLOPE * e; }

// ---------------- single-pass gather aggregation (bf16 h) ----------------
__global__ __launch_bounds__(256) void aggregate_kernel(const __nv_bfloat16* __restrict__ hbuf,
                                                        const float* __restrict__ asrc,
                                                        const float* __restrict__ adst,
                                                        const float* __restrict__ bias,
                                                        float* __restrict__ outbuf) {
    int w = (blockIdx.x * blockDim.x + threadIdx.x) >> 5;
    int lane = threadIdx.x & 31;
    if (w >= NN) return;
    int dst = w;
    int beg = g_rowptr[dst], end = g_rowptr[dst + 1];
    int hd = lane >> 2;           // head 0..7
    int cb = (lane & 3) * 8;      // channel base within head
    float adst_h = adst[dst * HH + hd];

    float ex_self = __expf(lrelu(asrc[dst * HH + hd] + adst_h));
    float s = ex_self;
    float acc[8];
    {
        uint4 raw = *(const uint4*)(hbuf + (size_t)dst * HC + hd * CC + cb);
        const __nv_bfloat162* p = (const __nv_bfloat162*)&raw;
#pragma unroll
        for (int t = 0; t < 4; t++) {
            float2 v = __bfloat1622float2(p[t]);
            acc[2 * t]     = ex_self * v.x;
            acc[2 * t + 1] = ex_self * v.y;
        }
    }

    for (int i = beg; i < end; ++i) {
        int src = g_csr[i];
        float ex = __expf(lrelu(asrc[src * HH + hd] + adst_h));
        s += ex;
        uint4 raw = *(const uint4*)(hbuf + (size_t)src * HC + hd * CC + cb);
        const __nv_bfloat162* p = (const __nv_bfloat162*)&raw;
#pragma unroll
        for (int t = 0; t < 4; t++) {
            float2 v = __bfloat1622float2(p[t]);
            acc[2 * t]     += ex * v.x;
            acc[2 * t + 1] += ex * v.y;
        }
    }

    float inv = 1.f / s;
#pragma unroll
    for (int j = 0; j < 8; j++) acc[j] *= inv;

#pragma unroll
    for (int j = 0; j < 8; j++) {
        float v = acc[j];
        v += __shfl_xor_sync(0xffffffffu, v, 4);
        v += __shfl_xor_sync(0xffffffffu, v, 8);
        v += __shfl_xor_sync(0xffffffffu, v, 16);
        acc[j] = v * 0.125f;
    }

    if (lane < 4) {
        float o[8];
#pragma unroll
        for (int j = 0; j < 8; j++) {
            float v = acc[j] + bias[cb + j];
            o[j] = v > 0.f ? v : (__expf(v) - 1.f);
        }
        float4* op = (float4*)(outbuf + (size_t)dst * CC + cb);
        op[0] = make_float4(o[0], o[1], o[2], o[3]);
        op[1] = make_float4(o[4], o[5], o[6], o[7]);
    }
}

// ---------------- final projection (32->40) + log_softmax ----------------
__global__ __launch_bounds__(128) void final_kernel(const float* __restrict__ act,
                                                    const float* __restrict__ Wo,
                                                    const float* __restrict__ bo,
                                                    float* __restrict__ out) {
    __shared__ float sW[CC * NOUT];
    __shared__ float sb[NOUT];
    for (int i = threadIdx.x; i < CC * NOUT; i += blockDim.x) sW[i] = Wo[i];
    for (int i = threadIdx.x; i < NOUT; i += blockDim.x) sb[i] = bo[i];
    __syncthreads();
    int n = blockIdx.x * blockDim.x + threadIdx.x;
    if (n >= NN) return;
    float xr[CC];
    const float4* ap = (const float4*)(act + (size_t)n * CC);
#pragma unroll
    for (int i = 0; i < 8; i++) {
        float4 v = ap[i];
        xr[4 * i + 0] = v.x; xr[4 * i + 1] = v.y; xr[4 * i + 2] = v.z; xr[4 * i + 3] = v.w;
    }
    float lg[NOUT];
#pragma unroll
    for (int j = 0; j < NOUT; j++) {
        float sum = sb[j];
#pragma unroll
        for (int c = 0; c < CC; c++) sum += xr[c] * sW[c * NOUT + j];
        lg[j] = sum;
    }
    float m = lg[0];
#pragma unroll
    for (int j = 1; j < NOUT; j++) m = fmaxf(m, lg[j]);
    float se = 0.f;
#pragma unroll
    for (int j = 0; j < NOUT; j++) se += __expf(lg[j] - m);
    float lse = m + __logf(se);
    float* op = out + (size_t)n * NOUT;
#pragma unroll
    for (int j = 0; j < NOUT; j++) op[j] = lg[j] - lse;
}

// ---------------- launch ----------------
extern "C" void kernel_launch(void* const* d_in, const int* in_sizes, int n_in,
                              void* d_out, int out_size) {
    const float* x   = (const float*)d_in[0];
    const int*   ei  = (const int*)d_in[1];
    const float* W1  = (const float*)d_in[2];
    const float* as1 = (const float*)d_in[3];
    const float* ad1 = (const float*)d_in[4];
    const float* b1  = (const float*)d_in[5];
    const float* W2  = (const float*)d_in[6];
    const float* as2 = (const float*)d_in[7];
    const float* ad2 = (const float*)d_in[8];
    const float* b2  = (const float*)d_in[9];
    const float* Wo  = (const float*)d_in[10];
    const float* bo  = (const float*)d_in[11];
    float* out = (float*)d_out;

    __nv_bfloat16* hbuf;
    float *act1, *act2, *pasrc, *padst;
    cudaGetSymbolAddress((void**)&hbuf, g_h);
    cudaGetSymbolAddress((void**)&act1, g_act1);
    cudaGetSymbolAddress((void**)&act2, g_act2);
    cudaGetSymbolAddress((void**)&pasrc, g_asrc);
    cudaGetSymbolAddress((void**)&padst, g_adst);

    // CSR build
    zero_kernel<<<NB, 256>>>();
    count_kernel<<<(EE + 255) / 256, 256>>>(ei);
    degsum_kernel<<<NB, 256>>>();
    scanb_kernel<<<1, 256>>>();
    scanc_kernel<<<NB, 256>>>();
    fill_kernel<<<(EE + 255) / 256, 256>>>(ei);

    dim3 gg(HC / GBN, (NN + GBM - 1) / GBM);

    // ---- layer 1 ----
    gemm_bf16<<<gg, 256>>>(x, W1, hbuf, NN, HC, FIN);
    alpha_kernel<<<(NN * HH + 255) / 256, 256>>>(hbuf, as1, ad1);
    aggregate_kernel<<<(NN * 32 + 255) / 256, 256>>>(hbuf, pasrc, padst, b1, act1);

    // ---- layer 2 ----
    gemm_bf16<<<gg, 256>>>(act1, W2, hbuf, NN, HC, CC);
    alpha_kernel<<<(NN * HH + 255) / 256, 256>>>(hbuf, as2, ad2);
    aggregate_kernel<<<(NN * 32 + 255) / 256, 256>>>(hbuf, pasrc, padst, b2, act2);

    // ---- output head ----
    final_kernel<<<(NN + 127) / 128, 128>>>(act2, Wo, bo, out);
}